// round 4
// baseline (speedup 1.0000x reference)
#include <cuda_runtime.h>
#include <math.h>

// Problem: B=64, V=8, J=17, H=256
// keypoints_gt: (B,V,J,2) float32   -> d_in[0], 17408 elems
// heatmap:      (B,V,1,H,H) float32 -> d_in[1], 33554432 elems
// out: scalar float = mean over B*V*J of -log(hm[b,v, clip(ceil(ky)), clip(ceil(kx))])

#define NTOT   8704      // 64*8*17
#define JDIM   17
#define HDIM   256
#define NBLK   68        // 68 * 128 = 8704 exactly
#define NTHR   128

__device__ float        g_partials[NBLK];
__device__ unsigned int g_flags[NBLK];     // zero-init at load; reset by poller each call

__device__ __forceinline__ unsigned int ld_acq(const unsigned int* p) {
    unsigned int v;
    asm volatile("ld.global.acquire.gpu.u32 %0, [%1];" : "=r"(v) : "l"(p) : "memory");
    return v;
}
__device__ __forceinline__ void st_rel(unsigned int* p, unsigned int v) {
    asm volatile("st.global.release.gpu.u32 [%0], %1;" :: "l"(p), "r"(v) : "memory");
}

__global__ __launch_bounds__(NTHR) void heatmap_ce_fused_kernel(
    const float* __restrict__ kp,   // (NTOT, 2)
    const float* __restrict__ hm,   // (B*V, H, H)
    float* __restrict__ out)
{
    const int i = blockIdx.x * NTHR + threadIdx.x;   // 0..8703, exact

    // coalesced float2 keypoint load
    const float2 k = reinterpret_cast<const float2*>(kp)[i];

    int xi = (int)ceilf(k.x);
    int yi = (int)ceilf(k.y);
    xi = min(max(xi, 0), HDIM - 1);
    yi = min(max(yi, 0), HDIM - 1);

    const int bv = i / JDIM;                         // (b*V + v)
    const long long off = (long long)bv * (HDIM * HDIM) + yi * HDIM + xi;

    const float val = __ldg(&hm[off]);
    float s = -__logf(val);   // vals in [0.001, 1]; fast log well within 1e-3 tol

    // warp reduce (5 levels)
    #pragma unroll
    for (int o = 16; o > 0; o >>= 1)
        s += __shfl_down_sync(0xFFFFFFFFu, s, o);

    __shared__ float sm[NTHR / 32];
    const int lane = threadIdx.x & 31;
    const int wid  = threadIdx.x >> 5;
    if (lane == 0) sm[wid] = s;
    __syncthreads();

    if (threadIdx.x == 0) {
        float bs = sm[0] + sm[1] + sm[2] + sm[3];
        g_partials[blockIdx.x] = bs;          // plain store ...
        st_rel(&g_flags[blockIdx.x], 1u);     // ... ordered by release flag
    }

    // Fixed poller: block 0, warp 0. Deterministic summation order.
    if (blockIdx.x == 0 && wid == 0) {
        // each lane owns flags lane, lane+32; lanes 0..3 also own lane+64
        bool d0 = false, d1 = false, d2 = (lane >= NBLK - 64);
        while (true) {
            if (!d0) d0 = (ld_acq(&g_flags[lane])      != 0u);
            if (!d1) d1 = (ld_acq(&g_flags[lane + 32]) != 0u);
            if (!d2) d2 = (ld_acq(&g_flags[lane + 64]) != 0u);
            if (__all_sync(0xFFFFFFFFu, d0 && d1 && d2)) break;
        }

        // parallel gather of partials in fixed order
        float s2 = g_partials[lane] + g_partials[lane + 32];
        if (lane < NBLK - 64) s2 += g_partials[lane + 64];

        #pragma unroll
        for (int o = 16; o > 0; o >>= 1)
            s2 += __shfl_down_sync(0xFFFFFFFFu, s2, o);

        if (lane == 0)
            out[0] = s2 * (1.0f / (float)NTOT);

        // rearm flags for next graph replay (kernel-boundary orders these
        // before the next replay's stores)
        g_flags[lane]      = 0u;
        g_flags[lane + 32] = 0u;
        if (lane < NBLK - 64) g_flags[lane + 64] = 0u;
    }
}

extern "C" void kernel_launch(void* const* d_in, const int* in_sizes, int n_in,
                              void* d_out, int out_size)
{
    const float* kp = (const float*)d_in[0];
    const float* hm = (const float*)d_in[1];
    float* out = (float*)d_out;

    heatmap_ce_fused_kernel<<<NBLK, NTHR>>>(kp, hm, out);
}

// round 5
// speedup vs baseline: 1.0385x; 1.0385x over previous
#include <cuda_runtime.h>
#include <math.h>

// Problem: B=64, V=8, J=17, H=256
// keypoints_gt: (B,V,J,2) float32   -> d_in[0], 17408 elems
// heatmap:      (B,V,1,H,H) float32 -> d_in[1], 33554432 elems
// out: scalar float = mean over B*V*J of -log(hm[b,v, clip(ceil(ky)), clip(ceil(kx))])

#define NTOT   8704      // 64*8*17
#define JDIM   17
#define HDIM   256
#define NBLK   272       // 272 * 32 = 8704 exactly; one warp per block
#define NTHR   32

// Partials double as completion flags: -log(val) > 0 strictly, so a finished
// partial can never be bit-pattern zero. Zero-initialized at module load;
// poller resets to zero each call for graph replays.
__device__ float g_partials[NBLK];   // zero-init

__device__ __forceinline__ float4 ld_relaxed_v4(const float4* p) {
    float4 v;
    asm volatile("ld.relaxed.gpu.global.v4.f32 {%0,%1,%2,%3}, [%4];"
                 : "=f"(v.x), "=f"(v.y), "=f"(v.z), "=f"(v.w)
                 : "l"(p) : "memory");
    return v;
}
__device__ __forceinline__ void st_relaxed(float* p, float v) {
    asm volatile("st.relaxed.gpu.global.f32 [%0], %1;" :: "l"(p), "f"(v) : "memory");
}

__global__ __launch_bounds__(NTHR) void heatmap_ce_fused_kernel(
    const float* __restrict__ kp,   // (NTOT, 2)
    const float* __restrict__ hm,   // (B*V, H, H)
    float* __restrict__ out)
{
    const int lane = threadIdx.x;                     // block == warp
    const int i = blockIdx.x * NTHR + lane;           // 0..8703, exact

    // coalesced float2 keypoint load
    const float2 k = reinterpret_cast<const float2*>(kp)[i];

    int xi = (int)ceilf(k.x);
    int yi = (int)ceilf(k.y);
    xi = min(max(xi, 0), HDIM - 1);
    yi = min(max(yi, 0), HDIM - 1);

    const int bv = i / JDIM;                          // (b*V + v)
    const long long off = (long long)bv * (HDIM * HDIM) + yi * HDIM + xi;

    const float val = __ldg(&hm[off]);
    float s = -__logf(val);    // strictly > 0; fast log well within 1e-3 tol

    // warp reduce (5 shfl levels) — no smem, no __syncthreads
    #pragma unroll
    for (int o = 16; o > 0; o >>= 1)
        s += __shfl_down_sync(0xFFFFFFFFu, s, o);

    if (lane == 0)
        st_relaxed(&g_partials[blockIdx.x], s);       // value IS the flag

    // Fixed poller: block 0's warp. 272 partials = 68 float4.
    // lane owns float4 indices: lane, lane+32, and (lanes 0..3) lane+64.
    if (blockIdx.x == 0) {
        const float4* p4 = reinterpret_cast<const float4*>(g_partials);
        float4 a, b, c;
        bool da = false, db = false, dc = (lane >= 68 - 64);
        c = make_float4(0.f, 0.f, 0.f, 0.f);
        while (true) {
            if (!da) { a = ld_relaxed_v4(&p4[lane]);
                       da = (a.x != 0.f) & (a.y != 0.f) & (a.z != 0.f) & (a.w != 0.f); }
            if (!db) { b = ld_relaxed_v4(&p4[lane + 32]);
                       db = (b.x != 0.f) & (b.y != 0.f) & (b.z != 0.f) & (b.w != 0.f); }
            if (!dc) { c = ld_relaxed_v4(&p4[lane + 64]);
                       dc = (c.x != 0.f) & (c.y != 0.f) & (c.z != 0.f) & (c.w != 0.f); }
            if (__all_sync(0xFFFFFFFFu, da && db && dc)) break;
        }

        // fixed-order summation (deterministic)
        float s2 = ((a.x + a.y) + (a.z + a.w))
                 + ((b.x + b.y) + (b.z + b.w))
                 + ((c.x + c.y) + (c.z + c.w));
        #pragma unroll
        for (int o = 16; o > 0; o >>= 1)
            s2 += __shfl_down_sync(0xFFFFFFFFu, s2, o);

        if (lane == 0)
            out[0] = s2 * (1.0f / (float)NTOT);

        // rearm sentinels for the next graph replay
        float4* q4 = reinterpret_cast<float4*>(g_partials);
        const float4 z = make_float4(0.f, 0.f, 0.f, 0.f);
        q4[lane]      = z;
        q4[lane + 32] = z;
        if (lane < 68 - 64) q4[lane + 64] = z;
    }
}

extern "C" void kernel_launch(void* const* d_in, const int* in_sizes, int n_in,
                              void* d_out, int out_size)
{
    const float* kp = (const float*)d_in[0];
    const float* hm = (const float*)d_in[1];
    float* out = (float*)d_out;

    heatmap_ce_fused_kernel<<<NBLK, NTHR>>>(kp, hm, out);
}